// round 14
// baseline (speedup 1.0000x reference)
#include <cuda_runtime.h>
#include <cuda_fp16.h>
#include <math.h>
#include <stdint.h>

// ---------------- problem dims ----------------
#define B_DIM 64
#define T_DIM 2048
#define D_DIM 256
#define M_DIM (B_DIM * T_DIM)   // 131072
#define EPS 1e-7f
#define WSCALE 16.0f
#define WSCALE_INV 0.0625f

// ---------------- GEMM tiling ----------------
#define BM 64
#define BK 32
#define NIT (D_DIM / BK)        // 8 k-chunks
#define NSTAGE_B 3
#define SA_B 80                 // smem row stride bytes (32 halves + 16B pad)

#define A_CH_BYTES (BM * SA_B)               // 5120 per k-chunk
#define A_TOTAL (NIT * A_CH_BYTES)           // 40960 (persistent)
#define B_ST_BYTES (256 * SA_B)              // 20480 per stage
#define A_CH(c) ((c) * A_CH_BYTES)
#define B_ST(s) (A_TOTAL + (s) * B_ST_BYTES)
#define SMEM_TOTAL (A_TOTAL + NSTAGE_B * B_ST_BYTES)   // 102400

// ---------------- scratch globals ----------------
__device__ float g_U[B_DIM * D_DIM];   // unnormalized output
__device__ float g_S[B_DIM];           // exp sums
__device__ int   g_cnt[B_DIM];         // per-batch completion counters
__device__ __align__(16) __half g_Wt[D_DIM * D_DIM];   // [n][k], W*16 fp16

// ---------------- helpers ----------------
__device__ __forceinline__ uint32_t smem_u32(const void* p) {
    uint32_t a;
    asm("{ .reg .u64 t; cvta.to.shared.u64 t, %1; cvt.u32.u64 %0, t; }"
        : "=r"(a) : "l"(p));
    return a;
}

__device__ __forceinline__ float tanh_fast(float x) {
    float y;
    asm("tanh.approx.f32 %0, %1;" : "=f"(y) : "f"(x));
    return y;
}

__device__ __forceinline__ void mma16816(float* c, const uint32_t* a,
                                         uint32_t b0, uint32_t b1) {
    asm volatile(
        "mma.sync.aligned.m16n8k16.row.col.f32.f16.f16.f32 "
        "{%0,%1,%2,%3}, {%4,%5,%6,%7}, {%8,%9}, {%0,%1,%2,%3};\n"
        : "+f"(c[0]), "+f"(c[1]), "+f"(c[2]), "+f"(c[3])
        : "r"(a[0]), "r"(a[1]), "r"(a[2]), "r"(a[3]), "r"(b0), "r"(b1));
}

__device__ __forceinline__ void ldsm_x4(uint32_t* r, uint32_t addr) {
    asm volatile("ldmatrix.sync.aligned.m8n8.x4.shared.b16 {%0,%1,%2,%3}, [%4];"
        : "=r"(r[0]), "=r"(r[1]), "=r"(r[2]), "=r"(r[3]) : "r"(addr));
}

__device__ __forceinline__ void cp_async16(uint32_t dst, const void* src) {
    asm volatile("cp.async.cg.shared.global [%0], [%1], 16;"
                 :: "r"(dst), "l"(src));
}
#define CP_COMMIT() asm volatile("cp.async.commit_group;" ::: "memory")
#define CP_WAIT1()  asm volatile("cp.async.wait_group 1;" ::: "memory")

// ---------------------------------------------------------------------------
// Prep: zero g_U/g_S/g_cnt; transpose W*16 into fp16 [n][k] via smem tiles.
// grid 64 (8x8 tiles of 32x32), block 256. Latency-bound -> more blocks.
// ---------------------------------------------------------------------------
__global__ void prep_kernel(const float* __restrict__ W) {
    __shared__ __half st[32][40];   // [k_local][n_local], padded
    const int kb = (blockIdx.x >> 3) * 32;
    const int nb = (blockIdx.x & 7) * 32;
    const int tid = threadIdx.x;

    // zero g_U (64 blocks * 256 threads = 16384) and g_S / g_cnt
    g_U[blockIdx.x * 256 + tid] = 0.0f;
    if (blockIdx.x == 0 && tid < B_DIM) {
        g_S[tid] = 0.0f;
        g_cnt[tid] = 0;
    }

    // load 32x32 fp32 tile coalesced (1 float4/thread), convert to smem
    const int r = tid >> 3;              // 0..31
    const int c4 = (tid & 7) * 4;        // 0..28
    float4 v = *(const float4*)&W[(kb + r) * D_DIM + nb + c4];
    st[r][c4 + 0] = __float2half_rn(v.x * WSCALE);
    st[r][c4 + 1] = __float2half_rn(v.y * WSCALE);
    st[r][c4 + 2] = __float2half_rn(v.z * WSCALE);
    st[r][c4 + 3] = __float2half_rn(v.w * WSCALE);
    __syncthreads();

    // write transposed, 8B per thread along k
    const int n = tid >> 3;              // 0..31
    const int kq = (tid & 7) * 4;        // 0..28
    union { __half h[4]; uint2 u; } t;
#pragma unroll
    for (int j = 0; j < 4; j++) t.h[j] = st[kq + j][n];
    *(uint2*)&g_Wt[(nb + n) * D_DIM + kb + kq] = t.u;
}

// ---------------------------------------------------------------------------
// Fused GEMM + tanh + uw-dot + exp + weighted-sum + last-CTA normalize.
// grid = M/64 = 2048, block = 256 (8 warps: 2m x 4n), warp tile 32x64.
// A persistent in smem (fp16), pipelined. B via 3-stage cp.async. 2 CTAs/SM.
// ---------------------------------------------------------------------------
__global__ __launch_bounds__(256, 2) void gemm_fused_kernel(
    const float* __restrict__ x,      // [M, 256]
    const float* __restrict__ bias,   // [256]
    const float* __restrict__ uw,     // [256]
    const int*   __restrict__ mask,   // [M]
    float*       __restrict__ out)    // [B, 256]
{
    extern __shared__ char smem[];
    __shared__ float red4[4][BM];
    __shared__ float sm_e[BM];
    __shared__ int is_last;
    const uint32_t sb = smem_u32(smem);
    const int tid = threadIdx.x;
    const int wid = tid >> 5;
    const int lane = tid & 31;
    const int wm = wid >> 2;       // 0..1
    const int wn = wid & 3;        // 0..3
    const int gid = lane >> 2;     // 0..7
    const int tg = lane & 3;       // 0..3
    const int m0 = blockIdx.x * BM;

    float acc[2][8][4];
#pragma unroll
    for (int mt = 0; mt < 2; mt++)
#pragma unroll
        for (int nt = 0; nt < 8; nt++)
#pragma unroll
            for (int r = 0; r < 4; r++) acc[mt][nt][r] = 0.0f;

    // ---- load indexing ----
    const int ar = tid >> 2;             // x row 0..63
    const int ak8 = (tid & 3) * 8;       // x k-offset within chunk (8 floats)
    const int wr0 = tid >> 2;            // W base row (then +i*64)
    const int wq = tid & 3;              // W 16B slice index

    // ---- ldmatrix addressing ----
    const uint32_t a_lds = sb + (wm * 32 + (lane & 15)) * SA_B + (lane >> 4) * 16;
    const int brow = wn * 64 + (lane & 7) + ((lane >> 4) << 3);  // + p*16
    const int bkh = (lane >> 3) & 1;

    float4 pa0, pa1;

#define LDG_A(c)                                                              \
    do {                                                                      \
        int k0 = (c) * BK;                                                    \
        pa0 = *(const float4*)&x[(size_t)(m0 + ar) * D_DIM + k0 + ak8];       \
        pa1 = *(const float4*)&x[(size_t)(m0 + ar) * D_DIM + k0 + ak8 + 4];   \
    } while (0)

#define STS_A(c)                                                              \
    do {                                                                      \
        union { __half2 h[4]; uint4 u; } hh;                                  \
        hh.h[0] = __floats2half2_rn(pa0.x, pa0.y);                            \
        hh.h[1] = __floats2half2_rn(pa0.z, pa0.w);                            \
        hh.h[2] = __floats2half2_rn(pa1.x, pa1.y);                            \
        hh.h[3] = __floats2half2_rn(pa1.z, pa1.w);                            \
        *(uint4*)(smem + A_CH(c) + ar * SA_B + ak8 * 2) = hh.u;               \
    } while (0)

#define CPB(c, s)                                                             \
    do {                                                                      \
        int k0 = (c) * BK;                                                    \
        _Pragma("unroll")                                                     \
        for (int i = 0; i < 4; i++) {                                         \
            int row = wr0 + i * 64;                                           \
            int q = wq ^ ((row >> 3) & 3);                                    \
            cp_async16(sb + B_ST(s) + row * SA_B + q * 16,                    \
                       &g_Wt[row * D_DIM + k0 + wq * 8]);                     \
        }                                                                     \
    } while (0)

    // prologue: B0/B1 in flight, A0 staged, A1 in regs
    CPB(0, 0); CP_COMMIT();
    CPB(1, 1); CP_COMMIT();
    LDG_A(0);
    STS_A(0);
    LDG_A(1);

#pragma unroll
    for (int c = 0; c < NIT; c++) {
        const int cur = c % NSTAGE_B;
        CP_WAIT1();                            // B of chunk c landed
        __syncthreads();                       // + A STS visible
        if (c + 1 < NIT) STS_A(c + 1);         // persistent slot c+1
        if (c + 2 < NIT) {
            CPB(c + 2, (c + 2) % NSTAGE_B);
            LDG_A(c + 2);
        }
        CP_COMMIT();                           // exactly one group per iter

        uint32_t a[2][2][4];
#pragma unroll
        for (int mt = 0; mt < 2; mt++)
#pragma unroll
            for (int ks = 0; ks < 2; ks++)
                ldsm_x4(a[mt][ks], a_lds + A_CH(c) + mt * 16 * SA_B + ks * 32);

#pragma unroll
        for (int p = 0; p < 4; p++) {
            int row = brow + p * 16;
            int x3 = (row >> 3) & 3;
            uint32_t baddr = sb + B_ST(cur) + row * SA_B;
            uint32_t b0[4], b1[4];
            ldsm_x4(b0, baddr + ((bkh + 0) ^ x3) * 16);
            ldsm_x4(b1, baddr + ((bkh + 2) ^ x3) * 16);
#pragma unroll
            for (int mt = 0; mt < 2; mt++) {
                mma16816(acc[mt][2 * p],     a[mt][0], b0[0], b0[1]);
                mma16816(acc[mt][2 * p + 1], a[mt][0], b0[2], b0[3]);
                mma16816(acc[mt][2 * p],     a[mt][1], b1[0], b1[1]);
                mma16816(acc[mt][2 * p + 1], a[mt][1], b1[2], b1[3]);
            }
        }
    }

    // ---- epilogue 1: score(m) = sum_n tanh(acc/16 + b[n]) * uw[n] ----
    float rowsum[4] = {0.f, 0.f, 0.f, 0.f};
#pragma unroll
    for (int nt = 0; nt < 8; nt++) {
        int c0 = wn * 64 + nt * 8 + tg * 2;
        float u0 = __ldg(&uw[c0]), u1 = __ldg(&uw[c0 + 1]);
        float b0 = __ldg(&bias[c0]), b1 = __ldg(&bias[c0 + 1]);
#pragma unroll
        for (int mt = 0; mt < 2; mt++) {
            rowsum[mt * 2 + 0] += tanh_fast(fmaf(acc[mt][nt][0], WSCALE_INV, b0)) * u0
                                + tanh_fast(fmaf(acc[mt][nt][1], WSCALE_INV, b1)) * u1;
            rowsum[mt * 2 + 1] += tanh_fast(fmaf(acc[mt][nt][2], WSCALE_INV, b0)) * u0
                                + tanh_fast(fmaf(acc[mt][nt][3], WSCALE_INV, b1)) * u1;
        }
    }
#pragma unroll
    for (int i = 0; i < 4; i++) {
        rowsum[i] += __shfl_xor_sync(0xffffffffu, rowsum[i], 1);
        rowsum[i] += __shfl_xor_sync(0xffffffffu, rowsum[i], 2);
    }
    if (tg == 0) {           // each (wm,wn) warp writes its 32 rows: no atomics
        red4[wn][wm * 32 + gid]          = rowsum[0];
        red4[wn][wm * 32 + gid + 8]      = rowsum[1];
        red4[wn][wm * 32 + 16 + gid]     = rowsum[2];
        red4[wn][wm * 32 + 16 + gid + 8] = rowsum[3];
    }
    __syncthreads();

    // ---- epilogue 2: e_t, S partial, U partial from persistent fp16 A ----
    const int b = m0 >> 11;   // 2048 rows per batch
    if (tid < BM) {
        float s = red4[0][tid] + red4[1][tid] + red4[2][tid] + red4[3][tid];
        float e = expf(s) * (float)mask[m0 + tid];
        sm_e[tid] = e;
#pragma unroll
        for (int off = 16; off > 0; off >>= 1)
            e += __shfl_xor_sync(0xffffffffu, e, off);
        if ((tid & 31) == 0) atomicAdd(&g_S[b], e);
    }
    __syncthreads();

    {
        const int d = tid;               // 0..255
        const int ch = d >> 5;           // k-chunk
        const int kk = d & 31;           // k within chunk
        const __half* col = (const __half*)(smem + A_CH(ch) + kk * 2);
        float u = 0.0f;
#pragma unroll 8
        for (int t = 0; t < BM; t++)
            u = fmaf(sm_e[t], __half2float(col[t * (SA_B / 2)]), u);
        atomicAdd(&g_U[b * D_DIM + d], u);
    }

    // ---- epilogue 3: last CTA of this batch normalizes and writes out ----
    __threadfence();
    __syncthreads();
    if (tid == 0)
        is_last = (atomicAdd(&g_cnt[b], 1) == (T_DIM / BM) - 1);
    __syncthreads();
    if (is_last) {
        __threadfence();
        float sden = g_S[b] + EPS;
        out[b * D_DIM + tid] = g_U[b * D_DIM + tid] / sden;
    }
}

// ---------------------------------------------------------------------------
extern "C" void kernel_launch(void* const* d_in, const int* in_sizes, int n_in,
                              void* d_out, int out_size) {
    const float* x    = (const float*)d_in[0];
    const float* W    = (const float*)d_in[1];
    const float* bias = (const float*)d_in[2];
    const float* uw   = (const float*)d_in[3];
    const int*   mask = (const int*)d_in[4];
    float* out = (float*)d_out;

    cudaFuncSetAttribute(gemm_fused_kernel,
                         cudaFuncAttributeMaxDynamicSharedMemorySize, SMEM_TOTAL);

    prep_kernel<<<64, 256>>>(W);

    gemm_fused_kernel<<<M_DIM / BM, 256, SMEM_TOTAL>>>(x, bias, uw, mask, out);
}

// round 15
// speedup vs baseline: 1.0561x; 1.0561x over previous
#include <cuda_runtime.h>
#include <cuda_fp16.h>
#include <math.h>
#include <stdint.h>

// ---------------- problem dims ----------------
#define B_DIM 64
#define T_DIM 2048
#define D_DIM 256
#define M_DIM (B_DIM * T_DIM)   // 131072
#define EPS 1e-7f
#define WSCALE 16.0f
#define WSCALE_INV 0.0625f

// ---------------- GEMM tiling ----------------
#define BM 64
#define BK 32
#define NIT (D_DIM / BK)        // 8 k-chunks
#define NSTAGE_B 3
#define SA_B 80                 // smem row stride bytes (32 halves + 16B pad)

#define A_CH_BYTES (BM * SA_B)               // 5120 per k-chunk
#define A_TOTAL (NIT * A_CH_BYTES)           // 40960 (persistent)
#define B_ST_BYTES (256 * SA_B)              // 20480 per stage
#define A_CH(c) ((c) * A_CH_BYTES)
#define B_ST(s) (A_TOTAL + (s) * B_ST_BYTES)
#define SMEM_TOTAL (A_TOTAL + NSTAGE_B * B_ST_BYTES)   // 102400

// ---------------- scratch globals ----------------
__device__ float g_U[B_DIM * D_DIM];   // unnormalized output
__device__ float g_S[B_DIM];           // exp sums
__device__ __align__(16) __half g_Wt[D_DIM * D_DIM];   // [n][k], W*16 fp16

// ---------------- helpers ----------------
__device__ __forceinline__ uint32_t smem_u32(const void* p) {
    uint32_t a;
    asm("{ .reg .u64 t; cvta.to.shared.u64 t, %1; cvt.u32.u64 %0, t; }"
        : "=r"(a) : "l"(p));
    return a;
}

__device__ __forceinline__ float tanh_fast(float x) {
    float y;
    asm("tanh.approx.f32 %0, %1;" : "=f"(y) : "f"(x));
    return y;
}

__device__ __forceinline__ void mma16816(float* c, const uint32_t* a,
                                         uint32_t b0, uint32_t b1) {
    asm volatile(
        "mma.sync.aligned.m16n8k16.row.col.f32.f16.f16.f32 "
        "{%0,%1,%2,%3}, {%4,%5,%6,%7}, {%8,%9}, {%0,%1,%2,%3};\n"
        : "+f"(c[0]), "+f"(c[1]), "+f"(c[2]), "+f"(c[3])
        : "r"(a[0]), "r"(a[1]), "r"(a[2]), "r"(a[3]), "r"(b0), "r"(b1));
}

__device__ __forceinline__ void ldsm_x4(uint32_t* r, uint32_t addr) {
    asm volatile("ldmatrix.sync.aligned.m8n8.x4.shared.b16 {%0,%1,%2,%3}, [%4];"
        : "=r"(r[0]), "=r"(r[1]), "=r"(r[2]), "=r"(r[3]) : "r"(addr));
}

__device__ __forceinline__ void cp_async16(uint32_t dst, const void* src) {
    asm volatile("cp.async.cg.shared.global [%0], [%1], 16;"
                 :: "r"(dst), "l"(src));
}
#define CP_COMMIT() asm volatile("cp.async.commit_group;" ::: "memory")
#define CP_WAIT1()  asm volatile("cp.async.wait_group 1;" ::: "memory")

// ---------------------------------------------------------------------------
// Prep: zero g_U/g_S; transpose W*16 into fp16 [n][k] via smem tiles.
// grid 64 (8x8 tiles of 32x32), block 256.
// ---------------------------------------------------------------------------
__global__ void prep_kernel(const float* __restrict__ W) {
    __shared__ __half st[32][40];   // [k_local][n_local], padded
    const int kb = (blockIdx.x >> 3) * 32;
    const int nb = (blockIdx.x & 7) * 32;
    const int tid = threadIdx.x;

    g_U[blockIdx.x * 256 + tid] = 0.0f;
    if (blockIdx.x == 0 && tid < B_DIM) g_S[tid] = 0.0f;

    const int r = tid >> 3;              // 0..31
    const int c4 = (tid & 7) * 4;        // 0..28
    float4 v = *(const float4*)&W[(kb + r) * D_DIM + nb + c4];
    st[r][c4 + 0] = __float2half_rn(v.x * WSCALE);
    st[r][c4 + 1] = __float2half_rn(v.y * WSCALE);
    st[r][c4 + 2] = __float2half_rn(v.z * WSCALE);
    st[r][c4 + 3] = __float2half_rn(v.w * WSCALE);
    __syncthreads();

    const int n = tid >> 3;              // 0..31
    const int kq = (tid & 7) * 4;        // 0..28
    union { __half h[4]; uint2 u; } t;
#pragma unroll
    for (int j = 0; j < 4; j++) t.h[j] = st[kq + j][n];
    *(uint2*)&g_Wt[(nb + n) * D_DIM + kb + kq] = t.u;
}

// ---------------------------------------------------------------------------
// Fused GEMM + tanh + uw-dot + exp + weighted-sum partials.
// grid = M/64 = 2048, block = 256 (8 warps: 2m x 4n), warp tile 32x64.
// A persistent in smem (fp16), pipelined. B via 3-stage cp.async. 2 CTAs/SM.
// ---------------------------------------------------------------------------
__global__ __launch_bounds__(256, 2) void gemm_fused_kernel(
    const float* __restrict__ x,      // [M, 256]
    const float* __restrict__ bias,   // [256]
    const float* __restrict__ uw,     // [256]
    const int*   __restrict__ mask)   // [M]
{
    extern __shared__ char smem[];
    __shared__ float red4[4][BM];
    __shared__ float sm_e[BM];
    const uint32_t sb = smem_u32(smem);
    const int tid = threadIdx.x;
    const int wid = tid >> 5;
    const int lane = tid & 31;
    const int wm = wid >> 2;       // 0..1
    const int wn = wid & 3;        // 0..3
    const int gid = lane >> 2;     // 0..7
    const int tg = lane & 3;       // 0..3
    const int m0 = blockIdx.x * BM;

    float acc[2][8][4];
#pragma unroll
    for (int mt = 0; mt < 2; mt++)
#pragma unroll
        for (int nt = 0; nt < 8; nt++)
#pragma unroll
            for (int r = 0; r < 4; r++) acc[mt][nt][r] = 0.0f;

    // ---- load indexing ----
    const int ar = tid >> 2;             // x row 0..63
    const int ak8 = (tid & 3) * 8;       // x k-offset within chunk (8 floats)
    const int wr0 = tid >> 2;            // W base row (then +i*64)
    const int wq = tid & 3;              // W 16B slice index

    // ---- ldmatrix addressing ----
    const uint32_t a_lds = sb + (wm * 32 + (lane & 15)) * SA_B + (lane >> 4) * 16;
    const int brow = wn * 64 + (lane & 7) + ((lane >> 4) << 3);  // + p*16
    const int bkh = (lane >> 3) & 1;

    float4 pa0, pa1;

#define LDG_A(c)                                                              \
    do {                                                                      \
        int k0 = (c) * BK;                                                    \
        pa0 = *(const float4*)&x[(size_t)(m0 + ar) * D_DIM + k0 + ak8];       \
        pa1 = *(const float4*)&x[(size_t)(m0 + ar) * D_DIM + k0 + ak8 + 4];   \
    } while (0)

#define STS_A(c)                                                              \
    do {                                                                      \
        union { __half2 h[4]; uint4 u; } hh;                                  \
        hh.h[0] = __floats2half2_rn(pa0.x, pa0.y);                            \
        hh.h[1] = __floats2half2_rn(pa0.z, pa0.w);                            \
        hh.h[2] = __floats2half2_rn(pa1.x, pa1.y);                            \
        hh.h[3] = __floats2half2_rn(pa1.z, pa1.w);                            \
        *(uint4*)(smem + A_CH(c) + ar * SA_B + ak8 * 2) = hh.u;               \
    } while (0)

#define CPB(c, s)                                                             \
    do {                                                                      \
        int k0 = (c) * BK;                                                    \
        _Pragma("unroll")                                                     \
        for (int i = 0; i < 4; i++) {                                         \
            int row = wr0 + i * 64;                                           \
            int q = wq ^ ((row >> 3) & 3);                                    \
            cp_async16(sb + B_ST(s) + row * SA_B + q * 16,                    \
                       &g_Wt[row * D_DIM + k0 + wq * 8]);                     \
        }                                                                     \
    } while (0)

    // prologue: B0/B1 in flight, A0 staged, A1 in regs
    CPB(0, 0); CP_COMMIT();
    CPB(1, 1); CP_COMMIT();
    LDG_A(0);
    STS_A(0);
    LDG_A(1);

#pragma unroll
    for (int c = 0; c < NIT; c++) {
        const int cur = c % NSTAGE_B;
        CP_WAIT1();                            // B of chunk c landed
        __syncthreads();                       // + A STS visible
        if (c + 1 < NIT) STS_A(c + 1);         // persistent slot c+1
        if (c + 2 < NIT) {
            CPB(c + 2, (c + 2) % NSTAGE_B);
            LDG_A(c + 2);
        }
        CP_COMMIT();                           // exactly one group per iter

        uint32_t a[2][2][4];
#pragma unroll
        for (int mt = 0; mt < 2; mt++)
#pragma unroll
            for (int ks = 0; ks < 2; ks++)
                ldsm_x4(a[mt][ks], a_lds + A_CH(c) + mt * 16 * SA_B + ks * 32);

#pragma unroll
        for (int p = 0; p < 4; p++) {
            int row = brow + p * 16;
            int x3 = (row >> 3) & 3;
            uint32_t baddr = sb + B_ST(cur) + row * SA_B;
            uint32_t b0[4], b1[4];
            ldsm_x4(b0, baddr + ((bkh + 0) ^ x3) * 16);
            ldsm_x4(b1, baddr + ((bkh + 2) ^ x3) * 16);
#pragma unroll
            for (int mt = 0; mt < 2; mt++) {
                mma16816(acc[mt][2 * p],     a[mt][0], b0[0], b0[1]);
                mma16816(acc[mt][2 * p + 1], a[mt][0], b0[2], b0[3]);
                mma16816(acc[mt][2 * p],     a[mt][1], b1[0], b1[1]);
                mma16816(acc[mt][2 * p + 1], a[mt][1], b1[2], b1[3]);
            }
        }
    }

    // ---- epilogue 1: score(m) = sum_n tanh(acc/16 + b[n]) * uw[n] ----
    float rowsum[4] = {0.f, 0.f, 0.f, 0.f};
#pragma unroll
    for (int nt = 0; nt < 8; nt++) {
        int c0 = wn * 64 + nt * 8 + tg * 2;
        float u0 = __ldg(&uw[c0]), u1 = __ldg(&uw[c0 + 1]);
        float b0 = __ldg(&bias[c0]), b1 = __ldg(&bias[c0 + 1]);
#pragma unroll
        for (int mt = 0; mt < 2; mt++) {
            rowsum[mt * 2 + 0] += tanh_fast(fmaf(acc[mt][nt][0], WSCALE_INV, b0)) * u0
                                + tanh_fast(fmaf(acc[mt][nt][1], WSCALE_INV, b1)) * u1;
            rowsum[mt * 2 + 1] += tanh_fast(fmaf(acc[mt][nt][2], WSCALE_INV, b0)) * u0
                                + tanh_fast(fmaf(acc[mt][nt][3], WSCALE_INV, b1)) * u1;
        }
    }
#pragma unroll
    for (int i = 0; i < 4; i++) {
        rowsum[i] += __shfl_xor_sync(0xffffffffu, rowsum[i], 1);
        rowsum[i] += __shfl_xor_sync(0xffffffffu, rowsum[i], 2);
    }
    if (tg == 0) {           // each (wm,wn) warp owns its 32 rows: no atomics
        red4[wn][wm * 32 + gid]          = rowsum[0];
        red4[wn][wm * 32 + gid + 8]      = rowsum[1];
        red4[wn][wm * 32 + 16 + gid]     = rowsum[2];
        red4[wn][wm * 32 + 16 + gid + 8] = rowsum[3];
    }
    __syncthreads();

    // ---- epilogue 2: e_t, S partial, U partial from persistent fp16 A ----
    const int b = m0 >> 11;   // 2048 rows per batch
    if (tid < BM) {
        float s = red4[0][tid] + red4[1][tid] + red4[2][tid] + red4[3][tid];
        float e = expf(s) * (float)mask[m0 + tid];
        sm_e[tid] = e;
#pragma unroll
        for (int off = 16; off > 0; off >>= 1)
            e += __shfl_xor_sync(0xffffffffu, e, off);
        if ((tid & 31) == 0) atomicAdd(&g_S[b], e);
    }
    __syncthreads();

    {
        const int d = tid;               // 0..255
        const int ch = d >> 5;           // k-chunk
        const int kk = d & 31;           // k within chunk
        const __half* col = (const __half*)(smem + A_CH(ch) + kk * 2);
        float u = 0.0f;
#pragma unroll 8
        for (int t = 0; t < BM; t++)
            u = fmaf(sm_e[t], __half2float(col[t * (SA_B / 2)]), u);
        atomicAdd(&g_U[b * D_DIM + d], u);
    }
}

// ---------------------------------------------------------------------------
// Normalize: out[b,d] = U[b,d] / (S[b] + EPS)
// ---------------------------------------------------------------------------
__global__ void norm_kernel(float* __restrict__ out) {
    int i = blockIdx.x * blockDim.x + threadIdx.x;   // 0..16383
    out[i] = g_U[i] / (g_S[i >> 8] + EPS);
}

// ---------------------------------------------------------------------------
extern "C" void kernel_launch(void* const* d_in, const int* in_sizes, int n_in,
                              void* d_out, int out_size) {
    const float* x    = (const float*)d_in[0];
    const float* W    = (const float*)d_in[1];
    const float* bias = (const float*)d_in[2];
    const float* uw   = (const float*)d_in[3];
    const int*   mask = (const int*)d_in[4];
    float* out = (float*)d_out;

    cudaFuncSetAttribute(gemm_fused_kernel,
                         cudaFuncAttributeMaxDynamicSharedMemorySize, SMEM_TOTAL);

    prep_kernel<<<64, 256>>>(W);

    gemm_fused_kernel<<<M_DIM / BM, 256, SMEM_TOTAL>>>(x, bias, uw, mask);

    norm_kernel<<<B_DIM * D_DIM / 256, 256>>>(out);
}